// round 14
// baseline (speedup 1.0000x reference)
#include <cuda_runtime.h>
#include <cuda_fp16.h>
#include <cstdint>

#define Bq 4
#define Nq 8192
#define DIMq 1024
#define Hq 16
#define DHq 64
#define GSPLIT 16

// ---------------- device scratch (no allocation allowed) ----------------
__device__ float g_Gpart[GSPLIT][Bq * Hq * DHq * DHq];   // 16 MB
__device__ float g_M[Bq * Hq * DHq * DHq];               // 1 MB
__device__ __half g_Phi[Bq * DIMq * DIMq];               // 8 MB  Pt[b][n][k]
__device__ __half g_xhi[Bq * Nq * DIMq];                 // 64 MB

// ---------------- PTX helpers ----------------
__device__ __forceinline__ uint32_t smem_u32(const void* p) {
    uint32_t a;
    asm("{ .reg .u64 t; cvta.to.shared.u64 t, %1; cvt.u32.u64 %0, t; }" : "=r"(a) : "l"(p));
    return a;
}

__device__ __forceinline__ void cpasync16(uint32_t saddr, const void* gptr) {
    asm volatile("cp.async.cg.shared.global [%0], [%1], 16;" :: "r"(saddr), "l"(gptr));
}
#define CP_COMMIT() asm volatile("cp.async.commit_group;" ::: "memory")
#define CP_WAIT(n)  asm volatile("cp.async.wait_group %0;" :: "n"(n) : "memory")

__device__ __forceinline__ void ldsm4(uint32_t* r, uint32_t addr) {
    asm volatile("ldmatrix.sync.aligned.m8n8.x4.shared.b16 {%0,%1,%2,%3}, [%4];"
                 : "=r"(r[0]), "=r"(r[1]), "=r"(r[2]), "=r"(r[3]) : "r"(addr));
}

__device__ __forceinline__ void ldsm4t(uint32_t* r, uint32_t addr) {
    asm volatile("ldmatrix.sync.aligned.m8n8.x4.trans.shared.b16 {%0,%1,%2,%3}, [%4];"
                 : "=r"(r[0]), "=r"(r[1]), "=r"(r[2]), "=r"(r[3]) : "r"(addr));
}

__device__ __forceinline__ void mma16816(float* c, const uint32_t* a, const uint32_t* b) {
    asm volatile(
        "mma.sync.aligned.m16n8k16.row.col.f32.f16.f16.f32 "
        "{%0,%1,%2,%3}, {%4,%5,%6,%7}, {%8,%9}, {%0,%1,%2,%3};"
        : "+f"(c[0]), "+f"(c[1]), "+f"(c[2]), "+f"(c[3])
        : "r"(a[0]), "r"(a[1]), "r"(a[2]), "r"(a[3]), "r"(b[0]), "r"(b[1]));
}

// ============================================================
// Kernel 1 (fused): x -> fp16 conversion + HMMA Gram partials
// grid (64 bh, GSPLIT), 256 thr.
// ============================================================
__global__ __launch_bounds__(256) void gram_convert_kernel(const float* __restrict__ x) {
    __shared__ __align__(128) char gsm[2][16384];
    int bh = blockIdx.x;
    int sp = blockIdx.y;
    int b = bh >> 4, h = bh & 15;
    int tid = threadIdx.x;
    int warp = tid >> 5, lane = tid & 31;

    int d0 = (warp >> 1) * 16;
    int e0 = (warp & 1) * 32;

    size_t rowbase = (size_t)b * Nq + (size_t)sp * (Nq / GSPLIT);
    const float* xb = x + rowbase * DIMq + h * DHq;
    __half* xo = (__half*)g_xhi + rowbase * DIMq + h * DHq;

    int lf = tid & 15;
    int ln0 = tid >> 4;

    int a_n = (lane & 7) + ((lane >> 4) & 1) * 8;
    int a_cb = d0 * 2 + ((lane >> 3) & 1) * 16;
    int b_n = (lane & 7) + ((lane >> 3) & 1) * 8;
    int b_cb0 = e0 * 2 + ((lane >> 4) & 1) * 16;
    int b_cb1 = (e0 + 16) * 2 + ((lane >> 4) & 1) * 16;

    float c[4][4];
#pragma unroll
    for (int j = 0; j < 4; j++)
#pragma unroll
        for (int q = 0; q < 4; q++) c[j][q] = 0.f;

    const int TILES = (Nq / GSPLIT) / 128;  // 4
    uint32_t bufu[2] = { smem_u32(gsm[0]), smem_u32(gsm[1]) };

    float4 v[8];
#pragma unroll
    for (int ps = 0; ps < 8; ps++)
        v[ps] = *(const float4*)(xb + (size_t)(ln0 + 16 * ps) * DIMq + lf * 4);
#pragma unroll
    for (int ps = 0; ps < 8; ps++) {
        int n = ln0 + 16 * ps;
        __half2 h0 = __floats2half2_rn(v[ps].x, v[ps].y);
        __half2 h1 = __floats2half2_rn(v[ps].z, v[ps].w);
        uint2 pk = make_uint2(*(uint32_t*)&h0, *(uint32_t*)&h1);
        uint32_t gr = (uint32_t)(((lf >> 1) ^ (n & 7)) * 16 + (lf & 1) * 8);
        *(uint2*)(gsm[0] + n * 128 + gr) = pk;
        *(uint2*)(xo + (size_t)n * DIMq + lf * 4) = pk;
    }
    __syncthreads();

#pragma unroll 1
    for (int t = 0; t < TILES; t++) {
        if (t + 1 < TILES) {
#pragma unroll
            for (int ps = 0; ps < 8; ps++)
                v[ps] = *(const float4*)(xb + (size_t)((t + 1) * 128 + ln0 + 16 * ps) * DIMq + lf * 4);
        }
        uint32_t sb = bufu[t & 1];
#pragma unroll
        for (int ks = 0; ks < 8; ks++) {
            int n0 = ks * 16;
            uint32_t a[4], t0[4], t1[4];
            {
                int r = n0 + a_n;
                uint32_t ad = sb + r * 128 + (((((uint32_t)a_cb) >> 4) ^ (uint32_t)(r & 7)) << 4);
                ldsm4t(a, ad);
            }
            {
                int r = n0 + b_n;
                uint32_t ad0 = sb + r * 128 + (((((uint32_t)b_cb0) >> 4) ^ (uint32_t)(r & 7)) << 4);
                ldsm4t(t0, ad0);
                uint32_t ad1 = sb + r * 128 + (((((uint32_t)b_cb1) >> 4) ^ (uint32_t)(r & 7)) << 4);
                ldsm4t(t1, ad1);
            }
            uint32_t bf0[2] = { t0[0], t0[1] };
            uint32_t bf1[2] = { t0[2], t0[3] };
            uint32_t bf2[2] = { t1[0], t1[1] };
            uint32_t bf3[2] = { t1[2], t1[3] };
            mma16816(c[0], a, bf0);
            mma16816(c[1], a, bf1);
            mma16816(c[2], a, bf2);
            mma16816(c[3], a, bf3);
        }
        if (t + 1 < TILES) {
#pragma unroll
            for (int ps = 0; ps < 8; ps++) {
                int n = ln0 + 16 * ps;
                __half2 h0 = __floats2half2_rn(v[ps].x, v[ps].y);
                __half2 h1 = __floats2half2_rn(v[ps].z, v[ps].w);
                uint2 pk = make_uint2(*(uint32_t*)&h0, *(uint32_t*)&h1);
                uint32_t gr = (uint32_t)(((lf >> 1) ^ (n & 7)) * 16 + (lf & 1) * 8);
                *(uint2*)(gsm[(t + 1) & 1] + n * 128 + gr) = pk;
                *(uint2*)(xo + (size_t)((t + 1) * 128 + n) * DIMq + lf * 4) = pk;
            }
        }
        __syncthreads();
    }

    float* dst = g_Gpart[sp] + (size_t)bh * 4096;
    int g = lane >> 2, tq = lane & 3;
#pragma unroll
    for (int j = 0; j < 4; j++) {
        int e = e0 + 8 * j + 2 * tq;
        *(float2*)(dst + (d0 + g) * 64 + e) = make_float2(c[j][0], c[j][1]);
        *(float2*)(dst + (d0 + g + 8) * 64 + e) = make_float2(c[j][2], c[j][3]);
    }
}

// ============================================================
// Kernel 2: computeM — reduce Gpart inline + chain, once per bh
// 64 blocks, 512 threads, dyn smem 49920 B
// ============================================================
__global__ __launch_bounds__(512) void computeM_kernel(const float* __restrict__ Wq,
                                                       const float* __restrict__ Wk,
                                                       const float* __restrict__ Wv) {
    extern __shared__ float sm[];
    float* sA = sm;            // 64x65
    float* sB = sm + 4160;
    float* sC = sm + 8320;
    int bh = blockIdx.x;
    int tid = threadIdx.x;
    int ty = tid >> 5;   // 0..15 -> rows ty*4..+3
    int tx = tid & 31;   // 0..31 -> cols tx*2..+1

    for (int i = tid; i < 4096; i += 512) {
        float s = 0.f;
#pragma unroll
        for (int p = 0; p < GSPLIT; p++) s += g_Gpart[p][(size_t)bh * 4096 + i];
        int r = i >> 6, c = i & 63;
        sA[r * 65 + c] = s;
        sB[r * 65 + c] = Wv[i];
    }
    __syncthreads();

    float acc[4][2];
    // Phase 1: T1[f][e] = sum_g G[f][g]*Wv[e][g] -> sC
#pragma unroll
    for (int i = 0; i < 4; i++) { acc[i][0] = 0.f; acc[i][1] = 0.f; }
#pragma unroll 4
    for (int g = 0; g < 64; g++) {
        float a[4], bb[2];
#pragma unroll
        for (int i = 0; i < 4; i++) a[i] = sA[(ty * 4 + i) * 65 + g];
#pragma unroll
        for (int j = 0; j < 2; j++) bb[j] = sB[(tx * 2 + j) * 65 + g];
#pragma unroll
        for (int i = 0; i < 4; i++) {
            acc[i][0] += a[i] * bb[0];
            acc[i][1] += a[i] * bb[1];
        }
    }
    __syncthreads();
#pragma unroll
    for (int i = 0; i < 4; i++) {
        sC[(ty * 4 + i) * 65 + tx * 2 + 0] = acc[i][0];
        sC[(ty * 4 + i) * 65 + tx * 2 + 1] = acc[i][1];
    }
    for (int i = tid; i < 4096; i += 512) {
        int r = i >> 6, c = i & 63;
        sA[r * 65 + c] = Wk[i];
    }
    __syncthreads();

    // Phase 2: T2[d][e] = sum_f Wk[d][f]*T1[f][e] -> sB
#pragma unroll
    for (int i = 0; i < 4; i++) { acc[i][0] = 0.f; acc[i][1] = 0.f; }
#pragma unroll 4
    for (int f = 0; f < 64; f++) {
        float a[4], bb[2];
#pragma unroll
        for (int i = 0; i < 4; i++) a[i] = sA[(ty * 4 + i) * 65 + f];
#pragma unroll
        for (int j = 0; j < 2; j++) bb[j] = sC[f * 65 + tx * 2 + j];
#pragma unroll
        for (int i = 0; i < 4; i++) {
            acc[i][0] += a[i] * bb[0];
            acc[i][1] += a[i] * bb[1];
        }
    }
    __syncthreads();
#pragma unroll
    for (int i = 0; i < 4; i++) {
        sB[(ty * 4 + i) * 65 + tx * 2 + 0] = acc[i][0];
        sB[(ty * 4 + i) * 65 + tx * 2 + 1] = acc[i][1];
    }
    for (int i = tid; i < 4096; i += 512) {
        int r = i >> 6, c = i & 63;
        sC[r * 65 + c] = Wq[i];
    }
    __syncthreads();

    // Phase 3: M[c][e] = (1/N) sum_d Wq[d][c]*T2[d][e]
#pragma unroll
    for (int i = 0; i < 4; i++) { acc[i][0] = 0.f; acc[i][1] = 0.f; }
#pragma unroll 4
    for (int d = 0; d < 64; d++) {
        float a[4], bb[2];
#pragma unroll
        for (int i = 0; i < 4; i++) a[i] = sC[d * 65 + ty * 4 + i];
#pragma unroll
        for (int j = 0; j < 2; j++) bb[j] = sB[d * 65 + tx * 2 + j];
#pragma unroll
        for (int i = 0; i < 4; i++) {
            acc[i][0] += a[i] * bb[0];
            acc[i][1] += a[i] * bb[1];
        }
    }
    const float sc = 1.0f / (float)Nq;
    float* Ms = g_M + (size_t)bh * 4096;
#pragma unroll
    for (int i = 0; i < 4; i++) {
        Ms[(ty * 4 + i) * 64 + tx * 2 + 0] = acc[i][0] * sc;
        Ms[(ty * 4 + i) * 64 + tx * 2 + 1] = acc[i][1] * sc;
    }
}

// ============================================================
// Kernel 3: expandP — Pt[b][i][h*64+c] = sum_e M[c][e] * Wo[i][h*64+e]
// grid (64 bh, 8), 256 thr, dyn smem 49920 B
// ============================================================
__global__ __launch_bounds__(256) void expandP_kernel(const float* __restrict__ Wo) {
    extern __shared__ float esm[];
    float* sM = esm;            // [c][e] stride 65
    float* sW = esm + 4160;     // [ii][e] stride 65 (128*65)
    int bh = blockIdx.x;
    int b = bh >> 4, h = bh & 15;
    int i0 = blockIdx.y * 128;
    int tid = threadIdx.x;
    const float* Ms = g_M + (size_t)bh * 4096;

    for (int i = tid; i < 4096; i += 256) {
        int r = i >> 6, c = i & 63;
        sM[r * 65 + c] = Ms[i];
    }
    for (int idx = tid; idx < 128 * 64; idx += 256) {
        int ii = idx >> 6, e = idx & 63;
        sW[ii * 65 + e] = Wo[(size_t)(i0 + ii) * DIMq + h * DHq + e];
    }
    __syncthreads();

    int ti = tid >> 3;  // 0..31 -> rows ii = ti*4..+3
    int tc = tid & 7;   // cols c = tc*8..+7
    float pacc[4][8];
#pragma unroll
    for (int i = 0; i < 4; i++)
#pragma unroll
        for (int j = 0; j < 8; j++) pacc[i][j] = 0.f;

#pragma unroll 4
    for (int e = 0; e < 64; e++) {
        float w[4], m[8];
#pragma unroll
        for (int i = 0; i < 4; i++) w[i] = sW[(ti * 4 + i) * 65 + e];
#pragma unroll
        for (int j = 0; j < 8; j++) m[j] = sM[(tc * 8 + j) * 65 + e];
#pragma unroll
        for (int i = 0; i < 4; i++)
#pragma unroll
            for (int j = 0; j < 8; j++) pacc[i][j] += w[i] * m[j];
    }
#pragma unroll
    for (int i = 0; i < 4; i++) {
        int ii = i0 + ti * 4 + i;
#pragma unroll
        for (int j = 0; j < 8; j++) {
            size_t o = ((size_t)b << 20) + (size_t)ii * DIMq + (h * DHq + tc * 8 + j);
            g_Phi[o] = __float2half_rn(pacc[i][j]);
        }
    }
}

// ============================================================
// Kernel 4: fp16 HMMA GEMM  out[b] = xhi[b] @ Phi[b] + bo
// CTA 128x128, 256 thr, BK=32 stages, 6-stage pipe, 2 chunks per
// sync (one __syncthreads per 64 K-elements), 2 CTAs/SM.
// ============================================================
#define BM 128
#define BN 128
#define STAGE_BYTES 16384   // A 8K | B 8K
#define NSTAGES 6
#define KCHUNKS 32

__device__ __forceinline__ void issue_chunk(uint32_t sbase, const char* gA,
                                            const char* gB, int tid) {
#pragma unroll
    for (int j = 0; j < 2; j++) {
        int idx = j * 256 + tid;
        int row = idx >> 2, g = idx & 3;
        uint32_t so = row * 64 + (((g ^ ((row >> 1) & 3))) << 4);
        size_t go = (size_t)row * 2048 + g * 16;
        cpasync16(sbase + so, gA + go);
        cpasync16(sbase + 8192 + so, gB + go);
    }
}

__global__ __launch_bounds__(256, 2) void gemm_hmma_kernel(const float* __restrict__ bo,
                                                           float* __restrict__ out) {
    extern __shared__ __align__(128) char dsm[];
    uint32_t sbase = smem_u32(dsm);

    int tid = threadIdx.x;
    int warp = tid >> 5, lane = tid & 31;
    int wm = warp & 1;
    int wn = warp >> 1;
    int b = blockIdx.z;
    int m0 = blockIdx.y * BM;
    int n0 = blockIdx.x * BN;

    const char* gA = (const char*)g_xhi + (((size_t)b * Nq + m0) * DIMq) * 2;
    const char* gB = (const char*)g_Phi + (((size_t)b * DIMq + n0) * DIMq) * 2;

    float acc[4][4][4];
#pragma unroll
    for (int mt = 0; mt < 4; mt++)
#pragma unroll
        for (int j = 0; j < 4; j++)
#pragma unroll
            for (int q = 0; q < 4; q++) acc[mt][j][q] = 0.f;

    int rowA = wm * 64 + (lane & 15);
    int gA_  = (lane >> 4);
    int rowB = wn * 32 + ((lane >> 4) & 1) * 8 + (lane & 7);
    int gB_  = ((lane >> 3) & 1);

    // prologue: 4 chunks in flight
    issue_chunk(sbase + 0 * STAGE_BYTES, gA, gB, tid); CP_COMMIT();
    issue_chunk(sbase + 1 * STAGE_BYTES, gA + 64, gB + 64, tid); CP_COMMIT();
    issue_chunk(sbase + 2 * STAGE_BYTES, gA + 128, gB + 128, tid); CP_COMMIT();
    issue_chunk(sbase + 3 * STAGE_BYTES, gA + 192, gB + 192, tid); CP_COMMIT();

#pragma unroll 1
    for (int it = 0; it < KCHUNKS / 2; it++) {
        int ki = it * 2;
        CP_WAIT(2);            // chunks ki, ki+1 complete
        __syncthreads();       // also guards reuse of slots (ki+4)%6, (ki+5)%6

        // issue next two chunks
#pragma unroll
        for (int q = 0; q < 2; q++) {
            int kc = ki + 4 + q;
            if (kc < KCHUNKS) {
                int slot = kc % NSTAGES;
                size_t off = (size_t)kc * 64;
                issue_chunk(sbase + slot * STAGE_BYTES, gA + off, gB + off, tid);
            }
            CP_COMMIT();
        }

        // process chunks ki and ki+1
#pragma unroll
        for (int q = 0; q < 2; q++) {
            uint32_t st = sbase + ((ki + q) % NSTAGES) * STAGE_BYTES;
#pragma unroll
            for (int s = 0; s < 2; s++) {
                uint32_t bhf[4][2];
#pragma unroll
                for (int jt = 0; jt < 2; jt++) {
                    int r = rowB + jt * 16;
                    int gg = ((gB_ + 2 * s) ^ ((r >> 1) & 3)) << 4;
                    uint32_t t0[4];
                    ldsm4(t0, st + 8192 + r * 64 + gg);
                    bhf[jt * 2][0] = t0[0]; bhf[jt * 2][1] = t0[1];
                    bhf[jt * 2 + 1][0] = t0[2]; bhf[jt * 2 + 1][1] = t0[3];
                }
#pragma unroll
                for (int mt = 0; mt < 4; mt++) {
                    uint32_t ah[4];
                    int r = rowA + mt * 16;
                    int gg = ((gA_ + 2 * s) ^ ((r >> 1) & 3)) << 4;
                    ldsm4(ah, st + r * 64 + gg);
#pragma unroll
                    for (int j = 0; j < 4; j++) {
                        mma16816(acc[mt][j], ah, bhf[j]);
                    }
                }
            }
        }
    }

    int r0 = lane >> 2, cpair = (lane & 3) * 2;
#pragma unroll
    for (int j = 0; j < 4; j++) {
        int n = n0 + wn * 32 + j * 8 + cpair;
        float2 bb = *(const float2*)(bo + n);
#pragma unroll
        for (int mt = 0; mt < 4; mt++) {
            int m = m0 + wm * 64 + mt * 16 + r0;
            float2 o0 = make_float2(acc[mt][j][0] + bb.x, acc[mt][j][1] + bb.y);
            float2 o1 = make_float2(acc[mt][j][2] + bb.x, acc[mt][j][3] + bb.y);
            *(float2*)(out + ((size_t)b * Nq + m) * DIMq + n) = o0;
            *(float2*)(out + ((size_t)b * Nq + m + 8) * DIMq + n) = o1;
        }
    }
}

// ============================================================
extern "C" void kernel_launch(void* const* d_in, const int* in_sizes, int n_in,
                              void* d_out, int out_size) {
    (void)in_sizes; (void)n_in; (void)out_size;
    const float* x  = (const float*)d_in[0];
    const float* Wq = (const float*)d_in[1];
    const float* Wk = (const float*)d_in[2];
    const float* Wv = (const float*)d_in[3];
    const float* Wo = (const float*)d_in[4];
    const float* bo = (const float*)d_in[5];
    float* out = (float*)d_out;

    gram_convert_kernel<<<dim3(Bq * Hq, GSPLIT), 256>>>(x);
    cudaFuncSetAttribute(computeM_kernel, cudaFuncAttributeMaxDynamicSharedMemorySize, 49920);
    computeM_kernel<<<Bq * Hq, 512, 49920>>>(Wq, Wk, Wv);
    cudaFuncSetAttribute(expandP_kernel, cudaFuncAttributeMaxDynamicSharedMemorySize, 49920);
    expandP_kernel<<<dim3(Bq * Hq, 8), 256, 49920>>>(Wo);
    cudaFuncSetAttribute(gemm_hmma_kernel, cudaFuncAttributeMaxDynamicSharedMemorySize,
                         NSTAGES * STAGE_BYTES);
    gemm_hmma_kernel<<<dim3(DIMq / BN, Nq / BM, Bq), 256, NSTAGES * STAGE_BYTES>>>(bo, out);
}

// round 15
// speedup vs baseline: 1.0269x; 1.0269x over previous
#include <cuda_runtime.h>
#include <cuda_fp16.h>
#include <cstdint>

#define Bq 4
#define Nq 8192
#define DIMq 1024
#define Hq 16
#define DHq 64
#define GSPLIT 16

// ---------------- device scratch (no allocation allowed) ----------------
__device__ float g_Gpart[GSPLIT][Bq * Hq * DHq * DHq];   // 16 MB
__device__ float g_A0[DHq * DHq];                        // 16 KB: Wq^T @ Wk
__device__ float g_M[Bq * Hq * DHq * DHq];               // 1 MB
__device__ __half g_Phi[Bq * DIMq * DIMq];               // 8 MB  Pt[b][n][k]
__device__ __half g_xhi[Bq * Nq * DIMq];                 // 64 MB

// ---------------- PTX helpers ----------------
__device__ __forceinline__ uint32_t smem_u32(const void* p) {
    uint32_t a;
    asm("{ .reg .u64 t; cvta.to.shared.u64 t, %1; cvt.u32.u64 %0, t; }" : "=r"(a) : "l"(p));
    return a;
}

__device__ __forceinline__ void cpasync16(uint32_t saddr, const void* gptr) {
    asm volatile("cp.async.cg.shared.global [%0], [%1], 16;" :: "r"(saddr), "l"(gptr));
}
#define CP_COMMIT() asm volatile("cp.async.commit_group;" ::: "memory")
#define CP_WAIT(n)  asm volatile("cp.async.wait_group %0;" :: "n"(n) : "memory")

__device__ __forceinline__ void ldsm4(uint32_t* r, uint32_t addr) {
    asm volatile("ldmatrix.sync.aligned.m8n8.x4.shared.b16 {%0,%1,%2,%3}, [%4];"
                 : "=r"(r[0]), "=r"(r[1]), "=r"(r[2]), "=r"(r[3]) : "r"(addr));
}

__device__ __forceinline__ void ldsm4t(uint32_t* r, uint32_t addr) {
    asm volatile("ldmatrix.sync.aligned.m8n8.x4.trans.shared.b16 {%0,%1,%2,%3}, [%4];"
                 : "=r"(r[0]), "=r"(r[1]), "=r"(r[2]), "=r"(r[3]) : "r"(addr));
}

__device__ __forceinline__ void mma16816(float* c, const uint32_t* a, const uint32_t* b) {
    asm volatile(
        "mma.sync.aligned.m16n8k16.row.col.f32.f16.f16.f32 "
        "{%0,%1,%2,%3}, {%4,%5,%6,%7}, {%8,%9}, {%0,%1,%2,%3};"
        : "+f"(c[0]), "+f"(c[1]), "+f"(c[2]), "+f"(c[3])
        : "r"(a[0]), "r"(a[1]), "r"(a[2]), "r"(a[3]), "r"(b[0]), "r"(b[1]));
}

// ============================================================
// Kernel 1 (fused): x -> fp16 conversion + HMMA Gram partials
// grid (65, GSPLIT): bh<64 do gram; the single (64,0) block
// computes A0 = Wq^T @ Wk (bh-independent) — rides the gram wave free.
// ============================================================
__global__ __launch_bounds__(256) void gram_convert_kernel(const float* __restrict__ x,
                                                           const float* __restrict__ Wq,
                                                           const float* __restrict__ Wk) {
    __shared__ __align__(128) char gsm[33536];
    int bh = blockIdx.x;
    int sp = blockIdx.y;
    int tid = threadIdx.x;

    if (bh == 64) {
        if (sp != 0) return;
        // A0[c][f] = sum_d Wq[d][c] * Wk[d][f]; 4x4 register tiles
        float* fQ = (float*)gsm;             // [d][c] stride 65 (16640 B)
        float* fK = (float*)(gsm + 16640);   // [d][f] stride 65
        for (int i = tid; i < 4096; i += 256) {
            int r = i >> 6, c = i & 63;
            fQ[r * 65 + c] = Wq[i];
            fK[r * 65 + c] = Wk[i];
        }
        __syncthreads();
        int ty = tid >> 4, tx = tid & 15;
        float acc[4][4];
#pragma unroll
        for (int i = 0; i < 4; i++)
#pragma unroll
            for (int j = 0; j < 4; j++) acc[i][j] = 0.f;
#pragma unroll 4
        for (int d = 0; d < 64; d++) {
            float a[4], bb[4];
#pragma unroll
            for (int i = 0; i < 4; i++) a[i] = fQ[d * 65 + ty * 4 + i];
#pragma unroll
            for (int j = 0; j < 4; j++) bb[j] = fK[d * 65 + tx * 4 + j];
#pragma unroll
            for (int i = 0; i < 4; i++)
#pragma unroll
                for (int j = 0; j < 4; j++) acc[i][j] += a[i] * bb[j];
        }
#pragma unroll
        for (int i = 0; i < 4; i++)
#pragma unroll
            for (int j = 0; j < 4; j++)
                g_A0[(ty * 4 + i) * 64 + tx * 4 + j] = acc[i][j];
        return;
    }

    int b = bh >> 4, h = bh & 15;
    int warp = tid >> 5, lane = tid & 31;

    int d0 = (warp >> 1) * 16;
    int e0 = (warp & 1) * 32;

    size_t rowbase = (size_t)b * Nq + (size_t)sp * (Nq / GSPLIT);
    const float* xb = x + rowbase * DIMq + h * DHq;
    __half* xo = (__half*)g_xhi + rowbase * DIMq + h * DHq;

    int lf = tid & 15;
    int ln0 = tid >> 4;

    int a_n = (lane & 7) + ((lane >> 4) & 1) * 8;
    int a_cb = d0 * 2 + ((lane >> 3) & 1) * 16;
    int b_n = (lane & 7) + ((lane >> 3) & 1) * 8;
    int b_cb0 = e0 * 2 + ((lane >> 4) & 1) * 16;
    int b_cb1 = (e0 + 16) * 2 + ((lane >> 4) & 1) * 16;

    float c[4][4];
#pragma unroll
    for (int j = 0; j < 4; j++)
#pragma unroll
        for (int q = 0; q < 4; q++) c[j][q] = 0.f;

    const int TILES = (Nq / GSPLIT) / 128;  // 4
    uint32_t bufu[2] = { smem_u32(gsm), smem_u32(gsm + 16384) };

    float4 v[8];
#pragma unroll
    for (int ps = 0; ps < 8; ps++)
        v[ps] = *(const float4*)(xb + (size_t)(ln0 + 16 * ps) * DIMq + lf * 4);
#pragma unroll
    for (int ps = 0; ps < 8; ps++) {
        int n = ln0 + 16 * ps;
        __half2 h0 = __floats2half2_rn(v[ps].x, v[ps].y);
        __half2 h1 = __floats2half2_rn(v[ps].z, v[ps].w);
        uint2 pk = make_uint2(*(uint32_t*)&h0, *(uint32_t*)&h1);
        uint32_t gr = (uint32_t)(((lf >> 1) ^ (n & 7)) * 16 + (lf & 1) * 8);
        *(uint2*)(gsm + n * 128 + gr) = pk;
        *(uint2*)(xo + (size_t)n * DIMq + lf * 4) = pk;
    }
    __syncthreads();

#pragma unroll 1
    for (int t = 0; t < TILES; t++) {
        if (t + 1 < TILES) {
#pragma unroll
            for (int ps = 0; ps < 8; ps++)
                v[ps] = *(const float4*)(xb + (size_t)((t + 1) * 128 + ln0 + 16 * ps) * DIMq + lf * 4);
        }
        uint32_t sb = bufu[t & 1];
#pragma unroll
        for (int ks = 0; ks < 8; ks++) {
            int n0 = ks * 16;
            uint32_t a[4], t0[4], t1[4];
            {
                int r = n0 + a_n;
                uint32_t ad = sb + r * 128 + (((((uint32_t)a_cb) >> 4) ^ (uint32_t)(r & 7)) << 4);
                ldsm4t(a, ad);
            }
            {
                int r = n0 + b_n;
                uint32_t ad0 = sb + r * 128 + (((((uint32_t)b_cb0) >> 4) ^ (uint32_t)(r & 7)) << 4);
                ldsm4t(t0, ad0);
                uint32_t ad1 = sb + r * 128 + (((((uint32_t)b_cb1) >> 4) ^ (uint32_t)(r & 7)) << 4);
                ldsm4t(t1, ad1);
            }
            uint32_t bf0[2] = { t0[0], t0[1] };
            uint32_t bf1[2] = { t0[2], t0[3] };
            uint32_t bf2[2] = { t1[0], t1[1] };
            uint32_t bf3[2] = { t1[2], t1[3] };
            mma16816(c[0], a, bf0);
            mma16816(c[1], a, bf1);
            mma16816(c[2], a, bf2);
            mma16816(c[3], a, bf3);
        }
        if (t + 1 < TILES) {
#pragma unroll
            for (int ps = 0; ps < 8; ps++) {
                int n = ln0 + 16 * ps;
                __half2 h0 = __floats2half2_rn(v[ps].x, v[ps].y);
                __half2 h1 = __floats2half2_rn(v[ps].z, v[ps].w);
                uint2 pk = make_uint2(*(uint32_t*)&h0, *(uint32_t*)&h1);
                uint32_t gr = (uint32_t)(((lf >> 1) ^ (n & 7)) * 16 + (lf & 1) * 8);
                *(uint2*)(gsm + (((t + 1) & 1) ? 16384 : 0) + n * 128 + gr) = pk;
                *(uint2*)(xo + (size_t)((t + 1) * 128 + n) * DIMq + lf * 4) = pk;
            }
        }
        __syncthreads();
    }

    float* dst = g_Gpart[sp] + (size_t)bh * 4096;
    int g = lane >> 2, tq = lane & 3;
#pragma unroll
    for (int j = 0; j < 4; j++) {
        int e = e0 + 8 * j + 2 * tq;
        *(float2*)(dst + (d0 + g) * 64 + e) = make_float2(c[j][0], c[j][1]);
        *(float2*)(dst + (d0 + g + 8) * 64 + e) = make_float2(c[j][2], c[j][3]);
    }
}

// ============================================================
// Kernel 2: computeM — reduce Gpart inline + 2-phase chain
// M = A0 @ (G @ Wv^T) / N; 64 blocks, 512 threads, dyn smem 49920 B
// ============================================================
__global__ __launch_bounds__(512) void computeM_kernel(const float* __restrict__ Wv) {
    extern __shared__ float sm[];
    float* sA = sm;            // 64x65
    float* sB = sm + 4160;
    float* sC = sm + 8320;
    int bh = blockIdx.x;
    int tid = threadIdx.x;
    int ty = tid >> 5;   // 0..15 -> rows ty*4..+3
    int tx = tid & 31;   // 0..31 -> cols tx*2..+1

    for (int i = tid; i < 4096; i += 512) {
        float s = 0.f;
#pragma unroll
        for (int p = 0; p < GSPLIT; p++) s += g_Gpart[p][(size_t)bh * 4096 + i];
        int r = i >> 6, c = i & 63;
        sA[r * 65 + c] = s;
        sB[r * 65 + c] = Wv[i];
    }
    __syncthreads();

    float acc[4][2];
    // Phase 1: T1[f][e] = sum_g G[f][g]*Wv[e][g] -> sC
#pragma unroll
    for (int i = 0; i < 4; i++) { acc[i][0] = 0.f; acc[i][1] = 0.f; }
#pragma unroll 4
    for (int g = 0; g < 64; g++) {
        float a[4], bb[2];
#pragma unroll
        for (int i = 0; i < 4; i++) a[i] = sA[(ty * 4 + i) * 65 + g];
#pragma unroll
        for (int j = 0; j < 2; j++) bb[j] = sB[(tx * 2 + j) * 65 + g];
#pragma unroll
        for (int i = 0; i < 4; i++) {
            acc[i][0] += a[i] * bb[0];
            acc[i][1] += a[i] * bb[1];
        }
    }
    __syncthreads();
#pragma unroll
    for (int i = 0; i < 4; i++) {
        sC[(ty * 4 + i) * 65 + tx * 2 + 0] = acc[i][0];
        sC[(ty * 4 + i) * 65 + tx * 2 + 1] = acc[i][1];
    }
    // load A0 [c][f] into sA
    for (int i = tid; i < 4096; i += 512) {
        int r = i >> 6, c = i & 63;
        sA[r * 65 + c] = g_A0[i];
    }
    __syncthreads();

    // Phase 2: M[c][e] = (1/N) sum_f A0[c][f] * T1[f][e]
#pragma unroll
    for (int i = 0; i < 4; i++) { acc[i][0] = 0.f; acc[i][1] = 0.f; }
#pragma unroll 4
    for (int f = 0; f < 64; f++) {
        float a[4], bb[2];
#pragma unroll
        for (int i = 0; i < 4; i++) a[i] = sA[(ty * 4 + i) * 65 + f];
#pragma unroll
        for (int j = 0; j < 2; j++) bb[j] = sC[f * 65 + tx * 2 + j];
#pragma unroll
        for (int i = 0; i < 4; i++) {
            acc[i][0] += a[i] * bb[0];
            acc[i][1] += a[i] * bb[1];
        }
    }
    const float sc = 1.0f / (float)Nq;
    float* Ms = g_M + (size_t)bh * 4096;
#pragma unroll
    for (int i = 0; i < 4; i++) {
        Ms[(ty * 4 + i) * 64 + tx * 2 + 0] = acc[i][0] * sc;
        Ms[(ty * 4 + i) * 64 + tx * 2 + 1] = acc[i][1] * sc;
    }
}

// ============================================================
// Kernel 3: expandP — Pt[b][i][h*64+c] = sum_e M[c][e] * Wo[i][h*64+e]
// grid (64 bh, 8), 256 thr, dyn smem 49920 B
// ============================================================
__global__ __launch_bounds__(256) void expandP_kernel(const float* __restrict__ Wo) {
    extern __shared__ float esm[];
    float* sM = esm;            // [c][e] stride 65
    float* sW = esm + 4160;     // [ii][e] stride 65 (128*65)
    int bh = blockIdx.x;
    int b = bh >> 4, h = bh & 15;
    int i0 = blockIdx.y * 128;
    int tid = threadIdx.x;
    const float* Ms = g_M + (size_t)bh * 4096;

    for (int i = tid; i < 4096; i += 256) {
        int r = i >> 6, c = i & 63;
        sM[r * 65 + c] = Ms[i];
    }
    for (int idx = tid; idx < 128 * 64; idx += 256) {
        int ii = idx >> 6, e = idx & 63;
        sW[ii * 65 + e] = Wo[(size_t)(i0 + ii) * DIMq + h * DHq + e];
    }
    __syncthreads();

    int ti = tid >> 3;  // 0..31 -> rows ii = ti*4..+3
    int tc = tid & 7;   // cols c = tc*8..+7
    float pacc[4][8];
#pragma unroll
    for (int i = 0; i < 4; i++)
#pragma unroll
        for (int j = 0; j < 8; j++) pacc[i][j] = 0.f;

#pragma unroll 4
    for (int e = 0; e < 64; e++) {
        float w[4], m[8];
#pragma unroll
        for (int i = 0; i < 4; i++) w[i] = sW[(ti * 4 + i) * 65 + e];
#pragma unroll
        for (int j = 0; j < 8; j++) m[j] = sM[(tc * 8 + j) * 65 + e];
#pragma unroll
        for (int i = 0; i < 4; i++)
#pragma unroll
            for (int j = 0; j < 8; j++) pacc[i][j] += w[i] * m[j];
    }
#pragma unroll
    for (int i = 0; i < 4; i++) {
        int ii = i0 + ti * 4 + i;
#pragma unroll
        for (int j = 0; j < 8; j++) {
            size_t o = ((size_t)b << 20) + (size_t)ii * DIMq + (h * DHq + tc * 8 + j);
            g_Phi[o] = __float2half_rn(pacc[i][j]);
        }
    }
}

// ============================================================
// Kernel 4: fp16 HMMA GEMM  out[b] = xhi[b] @ Phi[b] + bo
// CTA 128x128, 256 thr, BK=32, 4-stage, 2 CTAs/SM [best measured]
// ============================================================
#define BM 128
#define BN 128
#define STAGE_BYTES 16384   // A 8K | B 8K
#define NSTAGES 4
#define KCHUNKS 32

__device__ __forceinline__ void issue_chunk(uint32_t sbase, const char* gA,
                                            const char* gB, int tid) {
#pragma unroll
    for (int j = 0; j < 2; j++) {
        int idx = j * 256 + tid;
        int row = idx >> 2, g = idx & 3;
        uint32_t so = row * 64 + (((g ^ ((row >> 1) & 3))) << 4);
        size_t go = (size_t)row * 2048 + g * 16;
        cpasync16(sbase + so, gA + go);
        cpasync16(sbase + 8192 + so, gB + go);
    }
}

__global__ __launch_bounds__(256, 2) void gemm_hmma_kernel(const float* __restrict__ bo,
                                                           float* __restrict__ out) {
    extern __shared__ __align__(128) char dsm[];
    uint32_t sbase = smem_u32(dsm);

    int tid = threadIdx.x;
    int warp = tid >> 5, lane = tid & 31;
    int wm = warp & 1;
    int wn = warp >> 1;
    int b = blockIdx.z;
    int m0 = blockIdx.y * BM;
    int n0 = blockIdx.x * BN;

    const char* gA = (const char*)g_xhi + (((size_t)b * Nq + m0) * DIMq) * 2;
    const char* gB = (const char*)g_Phi + (((size_t)b * DIMq + n0) * DIMq) * 2;

    float acc[4][4][4];
#pragma unroll
    for (int mt = 0; mt < 4; mt++)
#pragma unroll
        for (int j = 0; j < 4; j++)
#pragma unroll
            for (int q = 0; q < 4; q++) acc[mt][j][q] = 0.f;

    int rowA = wm * 64 + (lane & 15);
    int gA_  = (lane >> 4);
    int rowB = wn * 32 + ((lane >> 4) & 1) * 8 + (lane & 7);
    int gB_  = ((lane >> 3) & 1);

    issue_chunk(sbase + 0 * STAGE_BYTES, gA, gB, tid); CP_COMMIT();
    issue_chunk(sbase + 1 * STAGE_BYTES, gA + 64, gB + 64, tid); CP_COMMIT();
    issue_chunk(sbase + 2 * STAGE_BYTES, gA + 128, gB + 128, tid); CP_COMMIT();

#pragma unroll 1
    for (int ki = 0; ki < KCHUNKS; ki++) {
        CP_WAIT(2);
        __syncthreads();
        if (ki + 3 < KCHUNKS) {
            int slot = (ki + 3) & (NSTAGES - 1);
            size_t off = (size_t)(ki + 3) * 64;
            issue_chunk(sbase + slot * STAGE_BYTES, gA + off, gB + off, tid);
        }
        CP_COMMIT();

        uint32_t st = sbase + (ki & (NSTAGES - 1)) * STAGE_BYTES;
#pragma unroll
        for (int s = 0; s < 2; s++) {
            uint32_t bhf[4][2];
#pragma unroll
            for (int jt = 0; jt < 2; jt++) {
                int r = rowB + jt * 16;
                int gg = ((gB_ + 2 * s) ^ ((r >> 1) & 3)) << 4;
                uint32_t t0[4];
                ldsm4(t0, st + 8192 + r * 64 + gg);
                bhf[jt * 2][0] = t0[0]; bhf[jt * 2][1] = t0[1];
                bhf[jt * 2 + 1][0] = t0[2]; bhf[jt * 2 + 1][1] = t0[3];
            }
#pragma unroll
            for (int mt = 0; mt < 4; mt++) {
                uint32_t ah[4];
                int r = rowA + mt * 16;
                int gg = ((gA_ + 2 * s) ^ ((r >> 1) & 3)) << 4;
                ldsm4(ah, st + r * 64 + gg);
#pragma unroll
                for (int j = 0; j < 4; j++) {
                    mma16816(acc[mt][j], ah, bhf[j]);
                }
            }
        }
    }

    int r0 = lane >> 2, cpair = (lane & 3) * 2;
#pragma unroll
    for (int j = 0; j < 4; j++) {
        int n = n0 + wn * 32 + j * 8 + cpair;
        float2 bb = *(const float2*)(bo + n);
#pragma unroll
        for (int mt = 0; mt < 4; mt++) {
            int m = m0 + wm * 64 + mt * 16 + r0;
            float2 o0 = make_float2(acc[mt][j][0] + bb.x, acc[mt][j][1] + bb.y);
            float2 o1 = make_float2(acc[mt][j][2] + bb.x, acc[mt][j][3] + bb.y);
            *(float2*)(out + ((size_t)b * Nq + m) * DIMq + n) = o0;
            *(float2*)(out + ((size_t)b * Nq + m + 8) * DIMq + n) = o1;
        }
    }
}

// ============================================================
extern "C" void kernel_launch(void* const* d_in, const int* in_sizes, int n_in,
                              void* d_out, int out_size) {
    (void)in_sizes; (void)n_in; (void)out_size;
    const float* x  = (const float*)d_in[0];
    const float* Wq = (const float*)d_in[1];
    const float* Wk = (const float*)d_in[2];
    const float* Wv = (const float*)d_in[3];
    const float* Wo = (const float*)d_in[4];
    const float* bo = (const float*)d_in[5];
    float* out = (float*)d_out;

    gram_convert_kernel<<<dim3(Bq * Hq + 1, GSPLIT), 256>>>(x, Wq, Wk);
    cudaFuncSetAttribute(computeM_kernel, cudaFuncAttributeMaxDynamicSharedMemorySize, 49920);
    computeM_kernel<<<Bq * Hq, 512, 49920>>>(Wv);
    cudaFuncSetAttribute(expandP_kernel, cudaFuncAttributeMaxDynamicSharedMemorySize, 49920);
    expandP_kernel<<<dim3(Bq * Hq, 8), 256, 49920>>>(Wo);
    cudaFuncSetAttribute(gemm_hmma_kernel, cudaFuncAttributeMaxDynamicSharedMemorySize,
                         NSTAGES * STAGE_BYTES);
    gemm_hmma_kernel<<<dim3(DIMq / BN, Nq / BM, Bq), 256, NSTAGES * STAGE_BYTES>>>(bo, out);
}